// round 1
// baseline (speedup 1.0000x reference)
#include <cuda_runtime.h>
#include <cuda_bf16.h>
#include <math.h>
#include <stdint.h>

// ---------------- problem constants ----------------
#define NLEV 3
#define MAXHW 65536
#define TOPK 1000
#define NTOT 3000              // 3 * TOPK
#define NW 47                  // ceil(3000/64)
#define NMS_TH 0.6f
#define CONF_TH 0.05f

// ---------------- device scratch (no allocations allowed) ----------------
__device__ unsigned            g_bits [NLEV][MAXHW];
__device__ int                 g_label[NLEV][MAXHW];
__device__ unsigned            g_hist [NLEV][65536];
__device__ unsigned            g_thresh[NLEV];
__device__ int                 g_ncand[NLEV];
__device__ int                 g_cand [NLEV][MAXHW];
__device__ unsigned            t_bits [NTOT];
__device__ int                 t_label[NTOT];
__device__ float               t_box  [NTOT][4];
__device__ float               s_score[NTOT];
__device__ int                 s_label[NTOT];
__device__ float               s_box  [NTOT][4];
__device__ unsigned long long  g_mask [NTOT][NW];
__device__ unsigned long long  g_keep [NW];

// ---------------- kernels ----------------

__global__ void zero_kernel() {
    int i = blockIdx.x * blockDim.x + threadIdx.x;
    if (i < NLEV * 65536) ((unsigned*)g_hist)[i] = 0u;
    if (i < NLEV) g_ncand[i] = 0;
}

__device__ __forceinline__ float sigm(float x) { return 1.0f / (1.0f + expf(-x)); }

// decode: joint score max/argmax over 80 classes + histogram of score bits
__global__ void decode_kernel(const float* __restrict__ cls,
                              const float* __restrict__ ctn,
                              int HW, int lv) {
    int i = blockIdx.x * blockDim.x + threadIdx.x;
    if (i >= HW) return;
    float m = cls[i];
    int lab = 0;
    #pragma unroll 4
    for (int c = 1; c < 80; c++) {
        float v = cls[c * HW + i];
        if (v > m) { m = v; lab = c; }
    }
    float sc = sqrtf(sigm(m) * sigm(ctn[i]));
    unsigned b = __float_as_uint(sc);   // sc in (0,1): bits monotone in value
    g_bits[lv][i]  = b;
    g_label[lv][i] = lab;
    atomicAdd(&g_hist[lv][b >> 16], 1u);
}

// find per-level threshold bucket so that count(bits >= thresh) >= TOPK, tight
__global__ void thresh_kernel() {
    int lv = blockIdx.x;
    int tid = threadIdx.x;          // 1024 threads
    __shared__ unsigned segsum[1024];
    unsigned s = 0;
    #pragma unroll 4
    for (int b = 0; b < 64; b++) s += g_hist[lv][tid * 64 + b];
    segsum[tid] = s;
    __syncthreads();
    if (tid == 0) {
        unsigned cum = 0; int seg = 0; unsigned before = 0;
        for (int t = 1023; t >= 0; t--) {
            if (cum + segsum[t] >= (unsigned)TOPK) { seg = t; before = cum; break; }
            cum += segsum[t];
        }
        unsigned c2 = before; unsigned th = 0;
        for (int b = 63; b >= 0; b--) {
            c2 += g_hist[lv][seg * 64 + b];
            if (c2 >= (unsigned)TOPK) { th = ((unsigned)(seg * 64 + b)) << 16; break; }
        }
        g_thresh[lv] = th;
    }
}

__global__ void compact_kernel(int HW, int lv) {
    int i = blockIdx.x * blockDim.x + threadIdx.x;
    if (i >= HW) return;
    if (g_bits[lv][i] >= g_thresh[lv]) {
        int p = atomicAdd(&g_ncand[lv], 1);
        g_cand[lv][p] = i;
    }
}

// rank candidates (exact lax.top_k semantics: value desc, index asc), emit topk rows
__global__ void rank_level_kernel(const float* __restrict__ reg,
                                  const float* __restrict__ scales,
                                  int HW, int W, float stride, int lv) {
    int ncand = g_ncand[lv];
    if ((int)(blockIdx.x * blockDim.x) >= ncand) return;   // whole-block uniform
    int c = blockIdx.x * blockDim.x + threadIdx.x;
    __shared__ unsigned long long skey[256];
    bool active = (c < ncand);
    unsigned mybits = 0; int myidx = 0;
    unsigned long long mykey = 0;
    if (active) {
        myidx = g_cand[lv][c];
        mybits = g_bits[lv][myidx];
        mykey = ((unsigned long long)mybits << 32) | (unsigned)(~(unsigned)myidx);
    }
    int rank = 0;
    for (int base = 0; base < ncand; base += 256) {
        int j = base + (int)threadIdx.x;
        unsigned long long k = 0;
        if (j < ncand) {
            int ji = g_cand[lv][j];
            k = ((unsigned long long)g_bits[lv][ji] << 32) | (unsigned)(~(unsigned)ji);
        }
        __syncthreads();
        skey[threadIdx.x] = k;
        __syncthreads();
        int lim = min(256, ncand - base);
        if (active)
            for (int t = 0; t < lim; t++) rank += (skey[t] > mykey) ? 1 : 0;
    }
    if (active && rank < TOPK) {
        int o = lv * TOPK + rank;
        t_bits[o]  = mybits;
        t_label[o] = g_label[lv][myidx];
        float sc = scales[lv];
        int x = myidx % W, y = myidx / W;
        float ax = ((float)x + 0.5f) * stride;
        float ay = ((float)y + 0.5f) * stride;
        float r0 = fmaxf(reg[0 * HW + myidx] * sc, 0.0f) * stride;
        float r1 = fmaxf(reg[1 * HW + myidx] * sc, 0.0f) * stride;
        float r2 = fmaxf(reg[2 * HW + myidx] * sc, 0.0f) * stride;
        float r3 = fmaxf(reg[3 * HW + myidx] * sc, 0.0f) * stride;
        t_box[o][0] = ax - r0; t_box[o][1] = ay - r1;
        t_box[o][2] = ax + r2; t_box[o][3] = ay + r3;
    }
}

// stable argsort(-scores) over the 3000 concatenated entries via rank counting
__global__ void rank_global_kernel() {
    int g = blockIdx.x * blockDim.x + threadIdx.x;
    __shared__ unsigned long long skey[256];
    bool active = (g < NTOT);
    unsigned long long mykey = 0;
    if (active) mykey = ((unsigned long long)t_bits[g] << 32) | (unsigned)(~(unsigned)g);
    int rank = 0;
    for (int base = 0; base < NTOT; base += 256) {
        int j = base + (int)threadIdx.x;
        unsigned long long k = 0;
        if (j < NTOT) k = ((unsigned long long)t_bits[j] << 32) | (unsigned)(~(unsigned)j);
        __syncthreads();
        skey[threadIdx.x] = k;
        __syncthreads();
        int lim = min(256, NTOT - base);
        if (active)
            for (int t = 0; t < lim; t++) rank += (skey[t] > mykey) ? 1 : 0;
    }
    if (active) {
        s_score[rank] = __uint_as_float(t_bits[g]);
        s_label[rank] = t_label[g];
        s_box[rank][0] = t_box[g][0];
        s_box[rank][1] = t_box[g][1];
        s_box[rank][2] = t_box[g][2];
        s_box[rank][3] = t_box[g][3];
    }
}

// suppression bitmask: bit j (j>i) set iff IoU(i,j) > 0.6
__global__ void mask_kernel() {
    int w = blockIdx.x;                            // word 0..46
    int i = blockIdx.y * blockDim.x + threadIdx.x; // sorted index
    __shared__ float jb[64][4];
    __shared__ float ja[64];
    int jlim = min(64, NTOT - w * 64);
    if ((int)threadIdx.x < jlim) {
        int j = w * 64 + threadIdx.x;
        float x1 = s_box[j][0], y1 = s_box[j][1], x2 = s_box[j][2], y2 = s_box[j][3];
        jb[threadIdx.x][0] = x1; jb[threadIdx.x][1] = y1;
        jb[threadIdx.x][2] = x2; jb[threadIdx.x][3] = y2;
        ja[threadIdx.x] = (x2 - x1) * (y2 - y1);
    }
    __syncthreads();
    if (i >= NTOT) return;
    float ix1 = s_box[i][0], iy1 = s_box[i][1], ix2 = s_box[i][2], iy2 = s_box[i][3];
    float ia = (ix2 - ix1) * (iy2 - iy1);
    unsigned long long bits = 0;
    for (int b = 0; b < jlim; b++) {
        int j = w * 64 + b;
        if (j > i) {
            float xx1 = fmaxf(ix1, jb[b][0]);
            float yy1 = fmaxf(iy1, jb[b][1]);
            float xx2 = fminf(ix2, jb[b][2]);
            float yy2 = fminf(iy2, jb[b][3]);
            float ww = fmaxf(1e-10f, xx2 - xx1);
            float hh = fmaxf(1e-10f, yy2 - yy1);
            float inter = ww * hh;
            float iou = inter / (ia + ja[b] - inter + 1e-14f);
            if (iou > NMS_TH) bits |= (1ull << b);
        }
    }
    g_mask[i][w] = bits;
}

// sequential greedy NMS scan over the bitmask (single block, 64 threads)
__global__ void nms_kernel() {
    __shared__ unsigned long long remv[NW];
    __shared__ unsigned long long sh_kept;
    int tid = threadIdx.x;
    if (tid < NW) remv[tid] = 0ull;
    __syncthreads();
    for (int c = 0; c < NW; c++) {
        if (tid == 0) {
            unsigned long long r = remv[c], kept = 0;
            int base = c * 64;
            int lim = min(64, NTOT - base);
            for (int b = 0; b < lim; b++) {
                if (!((r >> b) & 1ull)) {
                    kept |= (1ull << b);
                    r |= g_mask[base + b][c];   // intra-word suppression (bits > b only)
                }
            }
            remv[c] = r;
            sh_kept = kept;
        }
        __syncthreads();
        unsigned long long kept = sh_kept;
        for (int w = c + 1 + tid; w < NW; w += (int)blockDim.x) {
            unsigned long long acc = remv[w];
            unsigned long long k = kept;
            while (k) {
                int b = __ffsll((long long)k) - 1;
                acc |= g_mask[c * 64 + b][w];
                k &= k - 1;
            }
            remv[w] = acc;
        }
        __syncthreads();
    }
    if (tid < NW) g_keep[tid] = remv[tid];
}

// final output write: [boxes 12000][scores 3000][labels 3000][keep 3000] all f32
__global__ void finalize_kernel(float* __restrict__ out) {
    int i = blockIdx.x * blockDim.x + threadIdx.x;
    if (i >= NTOT) return;
    out[i * 4 + 0] = s_box[i][0];
    out[i * 4 + 1] = s_box[i][1];
    out[i * 4 + 2] = s_box[i][2];
    out[i * 4 + 3] = s_box[i][3];
    float sc = s_score[i];
    out[12000 + i] = sc;
    out[15000 + i] = (float)s_label[i];
    bool kp = !((g_keep[i >> 6] >> (i & 63)) & 1ull) && (sc > CONF_TH);
    out[18000 + i] = kp ? 1.0f : 0.0f;
}

// ---------------- launch ----------------
extern "C" void kernel_launch(void* const* d_in, const int* in_sizes, int n_in,
                              void* d_out, int out_size) {
    // map inputs: sizes cls = {5242880,1310720,327680}, reg0=262144,
    // reg1/ctn0 = 65536, reg2/ctn1 = 16384, ctn2 = 4096, scales = 3.
    const float *cls[3], *reg[3], *ctn[3], *scales;
    if (in_sizes[1] == 262144) {
        // dict order: cls0, reg0, ctn0, cls1, reg1, ctn1, cls2, reg2, ctn2, scales
        cls[0] = (const float*)d_in[0]; reg[0] = (const float*)d_in[1]; ctn[0] = (const float*)d_in[2];
        cls[1] = (const float*)d_in[3]; reg[1] = (const float*)d_in[4]; ctn[1] = (const float*)d_in[5];
        cls[2] = (const float*)d_in[6]; reg[2] = (const float*)d_in[7]; ctn[2] = (const float*)d_in[8];
        scales = (const float*)d_in[9];
    } else if (in_sizes[3] == 262144) {
        // signature order: cls0..2, reg0..2, ctn0..2, scales
        cls[0] = (const float*)d_in[0]; cls[1] = (const float*)d_in[1]; cls[2] = (const float*)d_in[2];
        reg[0] = (const float*)d_in[3]; reg[1] = (const float*)d_in[4]; reg[2] = (const float*)d_in[5];
        ctn[0] = (const float*)d_in[6]; ctn[1] = (const float*)d_in[7]; ctn[2] = (const float*)d_in[8];
        scales = (const float*)d_in[9];
    } else {
        // alphabetical order: cls0..2, ctn0..2, reg0..2, scales
        cls[0] = (const float*)d_in[0]; cls[1] = (const float*)d_in[1]; cls[2] = (const float*)d_in[2];
        ctn[0] = (const float*)d_in[3]; ctn[1] = (const float*)d_in[4]; ctn[2] = (const float*)d_in[5];
        reg[0] = (const float*)d_in[6]; reg[1] = (const float*)d_in[7]; reg[2] = (const float*)d_in[8];
        scales = (const float*)d_in[9];
    }

    const int HW[3]     = {65536, 16384, 4096};
    const int Wd[3]     = {256, 128, 64};
    const float strd[3] = {8.0f, 16.0f, 32.0f};

    zero_kernel<<<(NLEV * 65536 + 255) / 256, 256>>>();
    for (int lv = 0; lv < 3; lv++)
        decode_kernel<<<(HW[lv] + 127) / 128, 128>>>(cls[lv], ctn[lv], HW[lv], lv);
    thresh_kernel<<<3, 1024>>>();
    for (int lv = 0; lv < 3; lv++)
        compact_kernel<<<(HW[lv] + 255) / 256, 256>>>(HW[lv], lv);
    for (int lv = 0; lv < 3; lv++)
        rank_level_kernel<<<(MAXHW + 255) / 256, 256>>>(reg[lv], scales, HW[lv], Wd[lv], strd[lv], lv);
    rank_global_kernel<<<(NTOT + 255) / 256, 256>>>();
    {
        dim3 grid(NW, (NTOT + 255) / 256);
        mask_kernel<<<grid, 256>>>();
    }
    nms_kernel<<<1, 64>>>();
    finalize_kernel<<<(NTOT + 255) / 256, 256>>>((float*)d_out);
}

// round 2
// speedup vs baseline: 3.6590x; 3.6590x over previous
#include <cuda_runtime.h>
#include <cuda_bf16.h>
#include <math.h>
#include <stdint.h>

// ---------------- problem constants ----------------
#define NLEV 3
#define MAXHW 65536
#define TOPK 1000
#define NTOT 3000              // 3 * TOPK
#define NW 47                  // ceil(3000/64)
#define NMS_TH 0.6f
#define CONF_TH 0.05f

// ---------------- device scratch (no allocations allowed) ----------------
__device__ unsigned            g_bits [NLEV][MAXHW];
__device__ int                 g_label[NLEV][MAXHW];
__device__ unsigned            g_hist [NLEV][65536];
__device__ unsigned            g_thresh[NLEV];
__device__ int                 g_ncand[NLEV];
__device__ int                 g_cand [NLEV][MAXHW];
__device__ unsigned            t_bits [NTOT];
__device__ int                 t_label[NTOT];
__device__ float               t_box  [NTOT][4];
__device__ float               s_score[NTOT];
__device__ int                 s_label[NTOT];
__device__ float               s_box  [NTOT][4];
__device__ unsigned long long  g_mask [NTOT][NW];
__device__ unsigned long long  g_keep [NW];

__constant__ int   c_HW[3]   = {65536, 16384, 4096};
__constant__ int   c_W[3]    = {256, 128, 64};
__constant__ float c_strd[3] = {8.0f, 16.0f, 32.0f};

// ---------------- kernels ----------------

__global__ void zero_kernel() {
    int i = blockIdx.x * blockDim.x + threadIdx.x;
    if (i < NLEV * 65536) ((unsigned*)g_hist)[i] = 0u;
    if (i < NLEV) g_ncand[i] = 0;
}

__device__ __forceinline__ float sigm(float x) { return 1.0f / (1.0f + expf(-x)); }

// fused decode for all 3 levels: joint score max/argmax over 80 classes + histogram
__global__ void decode_all_kernel(const float* __restrict__ cls0,
                                  const float* __restrict__ cls1,
                                  const float* __restrict__ cls2,
                                  const float* __restrict__ ctn0,
                                  const float* __restrict__ ctn1,
                                  const float* __restrict__ ctn2) {
    int blk = blockIdx.x;
    int lv; const float* cls; const float* ctn; int HW;
    if (blk < 512)      { lv = 0; cls = cls0; ctn = ctn0; HW = 65536; blk -= 0;   }
    else if (blk < 640) { lv = 1; cls = cls1; ctn = ctn1; HW = 16384; blk -= 512; }
    else                { lv = 2; cls = cls2; ctn = ctn2; HW = 4096;  blk -= 640; }
    int i = blk * 128 + threadIdx.x;
    if (i >= HW) return;

    float cv = ctn[i];

    // 4 independent max-chains (20 classes each) for MLP; tie -> smaller label
    float m[4]; int lab[4];
    #pragma unroll
    for (int k = 0; k < 4; k++) {
        int c0 = k * 20;
        m[k] = cls[c0 * HW + i]; lab[k] = c0;
        #pragma unroll
        for (int c = 1; c < 20; c++) {
            float v = cls[(c0 + c) * HW + i];
            if (v > m[k]) { m[k] = v; lab[k] = c0 + c; }
        }
    }
    float bm = m[0]; int bl = lab[0];
    #pragma unroll
    for (int k = 1; k < 4; k++) {
        if (m[k] > bm || (m[k] == bm && lab[k] < bl)) { bm = m[k]; bl = lab[k]; }
    }

    float sc = sqrtf(sigm(bm) * sigm(cv));
    unsigned b = __float_as_uint(sc);   // sc in (0,1): bits monotone in value
    g_bits[lv][i]  = b;
    g_label[lv][i] = bl;
    atomicAdd(&g_hist[lv][b >> 16], 1u);
}

// per-level threshold bucket so count(bits >= thresh) >= TOPK, tight
__global__ void thresh_kernel() {
    int lv = blockIdx.x;
    int tid = threadIdx.x;          // 1024 threads
    __shared__ unsigned segsum[1024];
    unsigned s = 0;
    #pragma unroll 4
    for (int b = 0; b < 64; b++) s += g_hist[lv][tid * 64 + b];
    segsum[tid] = s;
    __syncthreads();
    if (tid == 0) {
        unsigned cum = 0; int seg = 0; unsigned before = 0;
        for (int t = 1023; t >= 0; t--) {
            if (cum + segsum[t] >= (unsigned)TOPK) { seg = t; before = cum; break; }
            cum += segsum[t];
        }
        unsigned c2 = before; unsigned th = 0;
        for (int b = 63; b >= 0; b--) {
            c2 += g_hist[lv][seg * 64 + b];
            if (c2 >= (unsigned)TOPK) { th = ((unsigned)(seg * 64 + b)) << 16; break; }
        }
        g_thresh[lv] = th;
    }
}

__global__ void compact_all_kernel() {
    int lv = blockIdx.y;
    int HW = c_HW[lv];
    int i = blockIdx.x * blockDim.x + threadIdx.x;
    if (i >= HW) return;
    if (g_bits[lv][i] >= g_thresh[lv]) {
        int p = atomicAdd(&g_ncand[lv], 1);
        g_cand[lv][p] = i;
    }
}

// rank candidates (exact lax.top_k semantics: value desc, index asc), emit topk rows
__global__ void rank_level_all_kernel(const float* __restrict__ reg0,
                                      const float* __restrict__ reg1,
                                      const float* __restrict__ reg2,
                                      const float* __restrict__ scales) {
    int lv = blockIdx.y;
    const float* reg = (lv == 0) ? reg0 : (lv == 1) ? reg1 : reg2;
    int HW = c_HW[lv], W = c_W[lv];
    float stride = c_strd[lv];
    int ncand = g_ncand[lv];
    if ((int)(blockIdx.x * blockDim.x) >= ncand) return;   // whole-block uniform
    int c = blockIdx.x * blockDim.x + threadIdx.x;
    __shared__ unsigned long long skey[256];
    bool active = (c < ncand);
    unsigned mybits = 0; int myidx = 0;
    unsigned long long mykey = 0;
    if (active) {
        myidx = g_cand[lv][c];
        mybits = g_bits[lv][myidx];
        mykey = ((unsigned long long)mybits << 32) | (unsigned)(~(unsigned)myidx);
    }
    int rank = 0;
    for (int base = 0; base < ncand; base += 256) {
        int j = base + (int)threadIdx.x;
        unsigned long long k = 0;
        if (j < ncand) {
            int ji = g_cand[lv][j];
            k = ((unsigned long long)g_bits[lv][ji] << 32) | (unsigned)(~(unsigned)ji);
        }
        __syncthreads();
        skey[threadIdx.x] = k;
        __syncthreads();
        int lim = min(256, ncand - base);
        if (active)
            for (int t = 0; t < lim; t++) rank += (skey[t] > mykey) ? 1 : 0;
    }
    if (active && rank < TOPK) {
        int o = lv * TOPK + rank;
        t_bits[o]  = mybits;
        t_label[o] = g_label[lv][myidx];
        float sc = scales[lv];
        int x = myidx % W, y = myidx / W;
        float ax = ((float)x + 0.5f) * stride;
        float ay = ((float)y + 0.5f) * stride;
        float r0 = fmaxf(reg[0 * HW + myidx] * sc, 0.0f) * stride;
        float r1 = fmaxf(reg[1 * HW + myidx] * sc, 0.0f) * stride;
        float r2 = fmaxf(reg[2 * HW + myidx] * sc, 0.0f) * stride;
        float r3 = fmaxf(reg[3 * HW + myidx] * sc, 0.0f) * stride;
        t_box[o][0] = ax - r0; t_box[o][1] = ay - r1;
        t_box[o][2] = ax + r2; t_box[o][3] = ay + r3;
    }
}

// stable argsort(-scores) over the 3000 concatenated entries via rank counting
__global__ void rank_global_kernel() {
    int g = blockIdx.x * blockDim.x + threadIdx.x;
    __shared__ unsigned long long skey[256];
    bool active = (g < NTOT);
    unsigned long long mykey = 0;
    if (active) mykey = ((unsigned long long)t_bits[g] << 32) | (unsigned)(~(unsigned)g);
    int rank = 0;
    for (int base = 0; base < NTOT; base += 256) {
        int j = base + (int)threadIdx.x;
        unsigned long long k = 0;
        if (j < NTOT) k = ((unsigned long long)t_bits[j] << 32) | (unsigned)(~(unsigned)j);
        __syncthreads();
        skey[threadIdx.x] = k;
        __syncthreads();
        int lim = min(256, NTOT - base);
        if (active)
            for (int t = 0; t < lim; t++) rank += (skey[t] > mykey) ? 1 : 0;
    }
    if (active) {
        s_score[rank] = __uint_as_float(t_bits[g]);
        s_label[rank] = t_label[g];
        s_box[rank][0] = t_box[g][0];
        s_box[rank][1] = t_box[g][1];
        s_box[rank][2] = t_box[g][2];
        s_box[rank][3] = t_box[g][3];
    }
}

// suppression bitmask: bit j (j>i) set iff IoU(i,j) > 0.6
__global__ void mask_kernel() {
    int w = blockIdx.x;                            // word 0..46
    int i = blockIdx.y * blockDim.x + threadIdx.x; // sorted index
    __shared__ float jb[64][4];
    __shared__ float ja[64];
    int jlim = min(64, NTOT - w * 64);
    if ((int)threadIdx.x < jlim) {
        int j = w * 64 + threadIdx.x;
        float x1 = s_box[j][0], y1 = s_box[j][1], x2 = s_box[j][2], y2 = s_box[j][3];
        jb[threadIdx.x][0] = x1; jb[threadIdx.x][1] = y1;
        jb[threadIdx.x][2] = x2; jb[threadIdx.x][3] = y2;
        ja[threadIdx.x] = (x2 - x1) * (y2 - y1);
    }
    __syncthreads();
    if (i >= NTOT) return;
    float ix1 = s_box[i][0], iy1 = s_box[i][1], ix2 = s_box[i][2], iy2 = s_box[i][3];
    float ia = (ix2 - ix1) * (iy2 - iy1);
    unsigned long long bits = 0;
    for (int b = 0; b < jlim; b++) {
        int j = w * 64 + b;
        if (j > i) {
            float xx1 = fmaxf(ix1, jb[b][0]);
            float yy1 = fmaxf(iy1, jb[b][1]);
            float xx2 = fminf(ix2, jb[b][2]);
            float yy2 = fminf(iy2, jb[b][3]);
            float ww = fmaxf(1e-10f, xx2 - xx1);
            float hh = fmaxf(1e-10f, yy2 - yy1);
            float inter = ww * hh;
            float iou = inter / (ia + ja[b] - inter + 1e-14f);
            if (iou > NMS_TH) bits |= (1ull << b);
        }
    }
    g_mask[i][w] = bits;
}

// greedy NMS scan — 47 word-blocks; serial chain is ALU-only (masks pre-staged in smem)
__global__ void nms_kernel() {
    __shared__ unsigned long long remv[NW];
    __shared__ unsigned long long col[64];
    __shared__ unsigned long long sh_kept;
    int tid = threadIdx.x;   // 256
    if (tid < NW) remv[tid] = 0ull;
    __syncthreads();
    for (int c = 0; c < NW; c++) {
        int base = c * 64;
        int lim = min(64, NTOT - base);
        // stage mask column c for rows [base, base+64) into smem (parallel loads)
        if (tid < 64) col[tid] = (tid < lim) ? g_mask[base + tid][c] : 0ull;
        __syncthreads();
        if (tid == 0) {
            unsigned long long r = remv[c], kept = 0;
            #pragma unroll
            for (int b = 0; b < 64; b++) {
                unsigned long long v = col[b];           // address indep of r -> pipelined
                if (!((r >> b) & 1ull)) { kept |= (1ull << b); r |= v; }
            }
            if (lim < 64) kept &= (1ull << lim) - 1ull;
            remv[c] = r;
            sh_kept = kept;
        }
        __syncthreads();
        unsigned long long kept = sh_kept;
        int nw_rem = NW - c - 1;
        // 4 threads per remaining word, each handles a 16-bit slice of kept
        for (int t = tid; t < nw_rem * 4; t += (int)blockDim.x) {
            int w = c + 1 + (t >> 2);
            int q = t & 3;
            unsigned long long k = kept & (0xFFFFull << (q * 16));
            unsigned long long acc = 0;
            while (k) {
                int b = __ffsll((long long)k) - 1;
                acc |= g_mask[base + b][w];
                k &= k - 1;
            }
            if (acc) atomicOr(&remv[w], acc);
        }
        __syncthreads();
    }
    if (tid < NW) g_keep[tid] = remv[tid];
}

// final output write: [boxes 12000][scores 3000][labels 3000][keep 3000] all f32
__global__ void finalize_kernel(float* __restrict__ out) {
    int i = blockIdx.x * blockDim.x + threadIdx.x;
    if (i >= NTOT) return;
    out[i * 4 + 0] = s_box[i][0];
    out[i * 4 + 1] = s_box[i][1];
    out[i * 4 + 2] = s_box[i][2];
    out[i * 4 + 3] = s_box[i][3];
    float sc = s_score[i];
    out[12000 + i] = sc;
    out[15000 + i] = (float)s_label[i];
    bool kp = !((g_keep[i >> 6] >> (i & 63)) & 1ull) && (sc > CONF_TH);
    out[18000 + i] = kp ? 1.0f : 0.0f;
}

// ---------------- launch ----------------
extern "C" void kernel_launch(void* const* d_in, const int* in_sizes, int n_in,
                              void* d_out, int out_size) {
    const float *cls[3], *reg[3], *ctn[3], *scales;
    if (in_sizes[1] == 262144) {
        cls[0] = (const float*)d_in[0]; reg[0] = (const float*)d_in[1]; ctn[0] = (const float*)d_in[2];
        cls[1] = (const float*)d_in[3]; reg[1] = (const float*)d_in[4]; ctn[1] = (const float*)d_in[5];
        cls[2] = (const float*)d_in[6]; reg[2] = (const float*)d_in[7]; ctn[2] = (const float*)d_in[8];
        scales = (const float*)d_in[9];
    } else if (in_sizes[3] == 262144) {
        cls[0] = (const float*)d_in[0]; cls[1] = (const float*)d_in[1]; cls[2] = (const float*)d_in[2];
        reg[0] = (const float*)d_in[3]; reg[1] = (const float*)d_in[4]; reg[2] = (const float*)d_in[5];
        ctn[0] = (const float*)d_in[6]; ctn[1] = (const float*)d_in[7]; ctn[2] = (const float*)d_in[8];
        scales = (const float*)d_in[9];
    } else {
        cls[0] = (const float*)d_in[0]; cls[1] = (const float*)d_in[1]; cls[2] = (const float*)d_in[2];
        ctn[0] = (const float*)d_in[3]; ctn[1] = (const float*)d_in[4]; ctn[2] = (const float*)d_in[5];
        reg[0] = (const float*)d_in[6]; reg[1] = (const float*)d_in[7]; reg[2] = (const float*)d_in[8];
        scales = (const float*)d_in[9];
    }

    zero_kernel<<<(NLEV * 65536 + 255) / 256, 256>>>();
    decode_all_kernel<<<512 + 128 + 32, 128>>>(cls[0], cls[1], cls[2],
                                               ctn[0], ctn[1], ctn[2]);
    thresh_kernel<<<3, 1024>>>();
    {
        dim3 g(256, 3);
        compact_all_kernel<<<g, 256>>>();
        rank_level_all_kernel<<<g, 256>>>(reg[0], reg[1], reg[2], scales);
    }
    rank_global_kernel<<<(NTOT + 255) / 256, 256>>>();
    {
        dim3 grid(NW, (NTOT + 255) / 256);
        mask_kernel<<<grid, 256>>>();
    }
    nms_kernel<<<1, 256>>>();
    finalize_kernel<<<(NTOT + 255) / 256, 256>>>((float*)d_out);
}

// round 4
// speedup vs baseline: 3.7483x; 1.0244x over previous
#include <cuda_runtime.h>
#include <cuda_bf16.h>
#include <math.h>
#include <stdint.h>

// ---------------- problem constants ----------------
#define NLEV 3
#define MAXHW 65536
#define TOPK 1000
#define NTOT 3000              // 3 * TOPK
#define NW 47                  // ceil(3000/64)
#define NMS_TH 0.6f
#define CONF_TH 0.05f

// ---------------- device scratch (no allocations allowed) ----------------
__device__ unsigned            g_bits [NLEV][MAXHW];
__device__ int                 g_label[NLEV][MAXHW];
__device__ unsigned            g_hist [NLEV][65536];
__device__ unsigned            g_thresh[NLEV];
__device__ int                 g_ncand[NLEV];
__device__ int                 g_cand [NLEV][MAXHW];
__device__ unsigned            t_bits [NTOT];
__device__ int                 t_label[NTOT];
__device__ float               t_box  [NTOT][4];
__device__ float               s_score[NTOT];
__device__ int                 s_label[NTOT];
__device__ float               s_box  [NTOT][4];
__device__ unsigned long long  g_mask [NTOT][NW];
__device__ unsigned long long  g_keep [NW];

__constant__ int   c_HW[3]   = {65536, 16384, 4096};
__constant__ int   c_W[3]    = {256, 128, 64};
__constant__ float c_strd[3] = {8.0f, 16.0f, 32.0f};

// ---------------- kernels ----------------

__global__ void zero_kernel() {
    int i = blockIdx.x * blockDim.x + threadIdx.x;
    if (i < NLEV * 65536) ((unsigned*)g_hist)[i] = 0u;
    if (i < NLEV) g_ncand[i] = 0;
}

__device__ __forceinline__ float sigm(float x) { return 1.0f / (1.0f + expf(-x)); }

// fused vectorized decode for all 3 levels: 4 pixels per thread via float4
__global__ void decode_all_kernel(const float* __restrict__ cls0,
                                  const float* __restrict__ cls1,
                                  const float* __restrict__ cls2,
                                  const float* __restrict__ ctn0,
                                  const float* __restrict__ ctn1,
                                  const float* __restrict__ ctn2) {
    int blk = blockIdx.x;
    int lv; const float* cls; const float* ctn; int HW;
    if (blk < 128)      { lv = 0; cls = cls0; ctn = ctn0; HW = 65536; }
    else if (blk < 160) { lv = 1; cls = cls1; ctn = ctn1; HW = 16384; blk -= 128; }
    else                { lv = 2; cls = cls2; ctn = ctn2; HW = 4096;  blk -= 160; }
    int HW4 = HW >> 2;
    int q = blk * 128 + threadIdx.x;     // float4 index
    if (q >= HW4) return;

    const float4* cls4 = (const float4*)cls;
    float4 cv = ((const float4*)ctn)[q];

    float4 m = cls4[q];
    int l0 = 0, l1 = 0, l2 = 0, l3 = 0;
    #pragma unroll 4
    for (int c = 1; c < 80; c++) {
        float4 v = cls4[c * HW4 + q];
        if (v.x > m.x) { m.x = v.x; l0 = c; }
        if (v.y > m.y) { m.y = v.y; l1 = c; }
        if (v.z > m.z) { m.z = v.z; l2 = c; }
        if (v.w > m.w) { m.w = v.w; l3 = c; }
    }

    unsigned b0 = __float_as_uint(sqrtf(sigm(m.x) * sigm(cv.x)));
    unsigned b1 = __float_as_uint(sqrtf(sigm(m.y) * sigm(cv.y)));
    unsigned b2 = __float_as_uint(sqrtf(sigm(m.z) * sigm(cv.z)));
    unsigned b3 = __float_as_uint(sqrtf(sigm(m.w) * sigm(cv.w)));

    ((uint4*)g_bits[lv])[q] = make_uint4(b0, b1, b2, b3);
    ((int4*)g_label[lv])[q] = make_int4(l0, l1, l2, l3);
    atomicAdd(&g_hist[lv][b0 >> 16], 1u);
    atomicAdd(&g_hist[lv][b1 >> 16], 1u);
    atomicAdd(&g_hist[lv][b2 >> 16], 1u);
    atomicAdd(&g_hist[lv][b3 >> 16], 1u);
}

// per-level threshold bucket so count(bits >= thresh) >= TOPK, tight
__global__ void thresh_kernel() {
    int lv = blockIdx.x;
    int tid = threadIdx.x;          // 1024 threads
    __shared__ unsigned segsum[1024];
    const uint4* h4 = (const uint4*)&g_hist[lv][tid * 64];
    unsigned s = 0;
    #pragma unroll
    for (int b = 0; b < 16; b++) { uint4 v = h4[b]; s += v.x + v.y + v.z + v.w; }
    segsum[tid] = s;
    __syncthreads();
    if (tid == 0) {
        unsigned cum = 0; int seg = 0; unsigned before = 0;
        for (int t = 1023; t >= 0; t--) {
            if (cum + segsum[t] >= (unsigned)TOPK) { seg = t; before = cum; break; }
            cum += segsum[t];
        }
        unsigned c2 = before; unsigned th = 0;
        for (int b = 63; b >= 0; b--) {
            c2 += g_hist[lv][seg * 64 + b];
            if (c2 >= (unsigned)TOPK) { th = ((unsigned)(seg * 64 + b)) << 16; break; }
        }
        g_thresh[lv] = th;
    }
}

__global__ void compact_all_kernel() {
    int lv = blockIdx.y;
    int HW = c_HW[lv];
    int i = blockIdx.x * blockDim.x + threadIdx.x;
    if (i >= HW) return;
    if (g_bits[lv][i] >= g_thresh[lv]) {
        int p = atomicAdd(&g_ncand[lv], 1);
        g_cand[lv][p] = i;
    }
}

// rank candidates (exact lax.top_k semantics: value desc, index asc), emit topk rows
__global__ void rank_level_all_kernel(const float* __restrict__ reg0,
                                      const float* __restrict__ reg1,
                                      const float* __restrict__ reg2,
                                      const float* __restrict__ scales) {
    int lv = blockIdx.y;
    const float* reg = (lv == 0) ? reg0 : (lv == 1) ? reg1 : reg2;
    int HW = c_HW[lv], W = c_W[lv];
    float stride = c_strd[lv];
    int ncand = g_ncand[lv];
    if ((int)(blockIdx.x * blockDim.x) >= ncand) return;   // whole-block uniform
    int c = blockIdx.x * blockDim.x + threadIdx.x;
    __shared__ unsigned long long skey[256];
    bool active = (c < ncand);
    unsigned mybits = 0; int myidx = 0;
    unsigned long long mykey = 0;
    if (active) {
        myidx = g_cand[lv][c];
        mybits = g_bits[lv][myidx];
        mykey = ((unsigned long long)mybits << 32) | (unsigned)(~(unsigned)myidx);
    }
    int rank = 0;
    for (int base = 0; base < ncand; base += 256) {
        int j = base + (int)threadIdx.x;
        unsigned long long k = 0;
        if (j < ncand) {
            int ji = g_cand[lv][j];
            k = ((unsigned long long)g_bits[lv][ji] << 32) | (unsigned)(~(unsigned)ji);
        }
        __syncthreads();
        skey[threadIdx.x] = k;
        __syncthreads();
        int lim = min(256, ncand - base);
        if (active)
            for (int t = 0; t < lim; t++) rank += (skey[t] > mykey) ? 1 : 0;
    }
    if (active && rank < TOPK) {
        int o = lv * TOPK + rank;
        t_bits[o]  = mybits;
        t_label[o] = g_label[lv][myidx];
        float sc = scales[lv];
        int x = myidx % W, y = myidx / W;
        float ax = ((float)x + 0.5f) * stride;
        float ay = ((float)y + 0.5f) * stride;
        float r0 = fmaxf(reg[0 * HW + myidx] * sc, 0.0f) * stride;
        float r1 = fmaxf(reg[1 * HW + myidx] * sc, 0.0f) * stride;
        float r2 = fmaxf(reg[2 * HW + myidx] * sc, 0.0f) * stride;
        float r3 = fmaxf(reg[3 * HW + myidx] * sc, 0.0f) * stride;
        t_box[o][0] = ax - r0; t_box[o][1] = ay - r1;
        t_box[o][2] = ax + r2; t_box[o][3] = ay + r3;
    }
}

// stable argsort(-scores) over the 3000 concatenated entries via rank counting
__global__ void rank_global_kernel() {
    int g = blockIdx.x * blockDim.x + threadIdx.x;
    __shared__ unsigned long long skey[256];
    bool active = (g < NTOT);
    unsigned long long mykey = 0;
    if (active) mykey = ((unsigned long long)t_bits[g] << 32) | (unsigned)(~(unsigned)g);
    int rank = 0;
    for (int base = 0; base < NTOT; base += 256) {
        int j = base + (int)threadIdx.x;
        unsigned long long k = 0;
        if (j < NTOT) k = ((unsigned long long)t_bits[j] << 32) | (unsigned)(~(unsigned)j);
        __syncthreads();
        skey[threadIdx.x] = k;
        __syncthreads();
        int lim = min(256, NTOT - base);
        if (active)
            for (int t = 0; t < lim; t++) rank += (skey[t] > mykey) ? 1 : 0;
    }
    if (active) {
        s_score[rank] = __uint_as_float(t_bits[g]);
        s_label[rank] = t_label[g];
        s_box[rank][0] = t_box[g][0];
        s_box[rank][1] = t_box[g][1];
        s_box[rank][2] = t_box[g][2];
        s_box[rank][3] = t_box[g][3];
    }
}

// suppression bitmask: bit j (j>i) set iff IoU(i,j) > 0.6
// triangle-pruned (skipped blocks are provably never read); round-2 exact IoU math
__global__ void mask_kernel() {
    int w  = blockIdx.x;                 // word 0..46  (j in [64w, 64w+64))
    int by = blockIdx.y;                 // i-block     (i in [256by, 256by+256))
    if (w < 4 * by) return;              // all j < all i in this block: never read
    __shared__ float jb[64][4];
    __shared__ float ja[64];
    int jlim = min(64, NTOT - w * 64);
    if ((int)threadIdx.x < jlim) {
        int j = w * 64 + threadIdx.x;
        float x1 = s_box[j][0], y1 = s_box[j][1], x2 = s_box[j][2], y2 = s_box[j][3];
        jb[threadIdx.x][0] = x1; jb[threadIdx.x][1] = y1;
        jb[threadIdx.x][2] = x2; jb[threadIdx.x][3] = y2;
        ja[threadIdx.x] = (x2 - x1) * (y2 - y1);
    }
    __syncthreads();
    int i = by * 256 + threadIdx.x;
    if (i >= NTOT) return;
    float ix1 = s_box[i][0], iy1 = s_box[i][1], ix2 = s_box[i][2], iy2 = s_box[i][3];
    float ia = (ix2 - ix1) * (iy2 - iy1);
    unsigned long long bits = 0;
    for (int b = 0; b < jlim; b++) {
        int j = w * 64 + b;
        if (j > i) {
            float xx1 = fmaxf(ix1, jb[b][0]);
            float yy1 = fmaxf(iy1, jb[b][1]);
            float xx2 = fminf(ix2, jb[b][2]);
            float yy2 = fminf(iy2, jb[b][3]);
            float ww = fmaxf(1e-10f, xx2 - xx1);
            float hh = fmaxf(1e-10f, yy2 - yy1);
            float inter = ww * hh;
            float iou = inter / (ia + ja[b] - inter + 1e-14f);
            if (iou > NMS_TH) bits |= (1ull << b);
        }
    }
    g_mask[i][w] = bits;
}

// greedy NMS scan — round-2 proven structure (single staged column, 3 syncs/iter)
__global__ void nms_kernel() {
    __shared__ unsigned long long remv[NW];
    __shared__ unsigned long long col[64];
    __shared__ unsigned long long sh_kept;
    int tid = threadIdx.x;   // 256
    if (tid < NW) remv[tid] = 0ull;
    __syncthreads();
    for (int c = 0; c < NW; c++) {
        int base = c * 64;
        int lim = min(64, NTOT - base);
        // stage mask column c for rows [base, base+64) into smem (parallel loads)
        if (tid < 64) col[tid] = (tid < lim) ? g_mask[base + tid][c] : 0ull;
        __syncthreads();
        if (tid == 0) {
            unsigned long long r = remv[c], kept = 0;
            #pragma unroll
            for (int b = 0; b < 64; b++) {
                unsigned long long v = col[b];           // address indep of r -> pipelined
                if (!((r >> b) & 1ull)) { kept |= (1ull << b); r |= v; }
            }
            if (lim < 64) kept &= (1ull << lim) - 1ull;
            remv[c] = r;
            sh_kept = kept;
        }
        __syncthreads();
        unsigned long long kept = sh_kept;
        int nw_rem = NW - c - 1;
        // 4 threads per remaining word, each handles a 16-bit slice of kept
        for (int t = tid; t < nw_rem * 4; t += (int)blockDim.x) {
            int w = c + 1 + (t >> 2);
            int q = t & 3;
            unsigned long long k = kept & (0xFFFFull << (q * 16));
            unsigned long long acc = 0;
            while (k) {
                int b = __ffsll((long long)k) - 1;
                acc |= g_mask[base + b][w];
                k &= k - 1;
            }
            if (acc) atomicOr(&remv[w], acc);
        }
        __syncthreads();
    }
    if (tid < NW) g_keep[tid] = remv[tid];
}

// final output write: [boxes 12000][scores 3000][labels 3000][keep 3000] all f32
__global__ void finalize_kernel(float* __restrict__ out) {
    int i = blockIdx.x * blockDim.x + threadIdx.x;
    if (i >= NTOT) return;
    out[i * 4 + 0] = s_box[i][0];
    out[i * 4 + 1] = s_box[i][1];
    out[i * 4 + 2] = s_box[i][2];
    out[i * 4 + 3] = s_box[i][3];
    float sc = s_score[i];
    out[12000 + i] = sc;
    out[15000 + i] = (float)s_label[i];
    bool kp = !((g_keep[i >> 6] >> (i & 63)) & 1ull) && (sc > CONF_TH);
    out[18000 + i] = kp ? 1.0f : 0.0f;
}

// ---------------- launch ----------------
extern "C" void kernel_launch(void* const* d_in, const int* in_sizes, int n_in,
                              void* d_out, int out_size) {
    const float *cls[3], *reg[3], *ctn[3], *scales;
    if (in_sizes[1] == 262144) {
        cls[0] = (const float*)d_in[0]; reg[0] = (const float*)d_in[1]; ctn[0] = (const float*)d_in[2];
        cls[1] = (const float*)d_in[3]; reg[1] = (const float*)d_in[4]; ctn[1] = (const float*)d_in[5];
        cls[2] = (const float*)d_in[6]; reg[2] = (const float*)d_in[7]; ctn[2] = (const float*)d_in[8];
        scales = (const float*)d_in[9];
    } else if (in_sizes[3] == 262144) {
        cls[0] = (const float*)d_in[0]; cls[1] = (const float*)d_in[1]; cls[2] = (const float*)d_in[2];
        reg[0] = (const float*)d_in[3]; reg[1] = (const float*)d_in[4]; reg[2] = (const float*)d_in[5];
        ctn[0] = (const float*)d_in[6]; ctn[1] = (const float*)d_in[7]; ctn[2] = (const float*)d_in[8];
        scales = (const float*)d_in[9];
    } else {
        cls[0] = (const float*)d_in[0]; cls[1] = (const float*)d_in[1]; cls[2] = (const float*)d_in[2];
        ctn[0] = (const float*)d_in[3]; ctn[1] = (const float*)d_in[4]; ctn[2] = (const float*)d_in[5];
        reg[0] = (const float*)d_in[6]; reg[1] = (const float*)d_in[7]; reg[2] = (const float*)d_in[8];
        scales = (const float*)d_in[9];
    }

    zero_kernel<<<(NLEV * 65536 + 255) / 256, 256>>>();
    decode_all_kernel<<<128 + 32 + 8, 128>>>(cls[0], cls[1], cls[2],
                                             ctn[0], ctn[1], ctn[2]);
    thresh_kernel<<<3, 1024>>>();
    {
        dim3 g(256, 3);
        compact_all_kernel<<<g, 256>>>();
        rank_level_all_kernel<<<g, 256>>>(reg[0], reg[1], reg[2], scales);
    }
    rank_global_kernel<<<(NTOT + 255) / 256, 256>>>();
    {
        dim3 grid(NW, (NTOT + 255) / 256);
        mask_kernel<<<grid, 256>>>();
    }
    nms_kernel<<<1, 256>>>();
    finalize_kernel<<<(NTOT + 255) / 256, 256>>>((float*)d_out);
}

// round 5
// speedup vs baseline: 3.8483x; 1.0267x over previous
#include <cuda_runtime.h>
#include <cuda_bf16.h>
#include <math.h>
#include <stdint.h>

// ---------------- problem constants ----------------
#define NLEV 3
#define MAXHW 65536
#define TOPK 1000
#define NTOT 3000              // 3 * TOPK
#define NW 47                  // ceil(3000/64)
#define NMS_TH 0.6f
#define CONF_TH 0.05f

// ---------------- device scratch (no allocations allowed) ----------------
__device__ unsigned            g_bits [NLEV][MAXHW];
__device__ int                 g_label[NLEV][MAXHW];
__device__ unsigned            g_hist [NLEV][65536];
__device__ unsigned            g_thresh[NLEV];
__device__ int                 g_ncand[NLEV];
__device__ int                 g_cand [NLEV][MAXHW];
__device__ unsigned            t_bits [NTOT];
__device__ int                 t_label[NTOT];
__device__ float               t_box  [NTOT][4];
__device__ float               s_score[NTOT];
__device__ int                 s_label[NTOT];
__device__ float               s_box  [NTOT][4];
__device__ unsigned long long  g_mask [NTOT][NW];
__device__ unsigned long long  g_keep [NW];

__constant__ int   c_HW[3]   = {65536, 16384, 4096};
__constant__ int   c_W[3]    = {256, 128, 64};
__constant__ float c_strd[3] = {8.0f, 16.0f, 32.0f};

// ---------------- kernels ----------------

__global__ void zero_kernel() {
    int i = blockIdx.x * blockDim.x + threadIdx.x;
    if (i < NLEV * 65536) ((unsigned*)g_hist)[i] = 0u;
    if (i < NLEV) g_ncand[i] = 0;
}

__device__ __forceinline__ float sigm(float x) { return 1.0f / (1.0f + expf(-x)); }

// fused decode, high-MLP: 1 thread/pixel, class loop in batches of 8
// independent loads (explicit MLP=8), 336 blocks (~18 warps/SM).
__global__ void __launch_bounds__(256) decode_all_kernel(
        const float* __restrict__ cls0,
        const float* __restrict__ cls1,
        const float* __restrict__ cls2,
        const float* __restrict__ ctn0,
        const float* __restrict__ ctn1,
        const float* __restrict__ ctn2) {
    int blk = blockIdx.x;
    int lv; const float* cls; const float* ctn; int HW;
    if (blk < 256)      { lv = 0; cls = cls0; ctn = ctn0; HW = 65536; }
    else if (blk < 320) { lv = 1; cls = cls1; ctn = ctn1; HW = 16384; blk -= 256; }
    else                { lv = 2; cls = cls2; ctn = ctn2; HW = 4096;  blk -= 320; }
    int i = blk * 256 + threadIdx.x;
    if (i >= HW) return;

    const float* p = cls + i;
    float m = -1e30f;
    int lab = 0;
    #pragma unroll
    for (int c0 = 0; c0 < 80; c0 += 8) {
        float v[8];
        #pragma unroll
        for (int k = 0; k < 8; k++) v[k] = p[(c0 + k) * HW];   // 8 independent loads
        #pragma unroll
        for (int k = 0; k < 8; k++)
            if (v[k] > m) { m = v[k]; lab = c0 + k; }          // in-order: first-max
    }

    float sc = sqrtf(sigm(m) * sigm(ctn[i]));
    unsigned b = __float_as_uint(sc);   // sc in (0,1): bits monotone in value
    g_bits[lv][i]  = b;
    g_label[lv][i] = lab;
    atomicAdd(&g_hist[lv][b >> 16], 1u);
}

// per-level threshold bucket so count(bits >= thresh) >= TOPK, tight
__global__ void thresh_kernel() {
    int lv = blockIdx.x;
    int tid = threadIdx.x;          // 1024 threads
    __shared__ unsigned segsum[1024];
    const uint4* h4 = (const uint4*)&g_hist[lv][tid * 64];
    unsigned s = 0;
    #pragma unroll
    for (int b = 0; b < 16; b++) { uint4 v = h4[b]; s += v.x + v.y + v.z + v.w; }
    segsum[tid] = s;
    __syncthreads();
    if (tid == 0) {
        unsigned cum = 0; int seg = 0; unsigned before = 0;
        for (int t = 1023; t >= 0; t--) {
            if (cum + segsum[t] >= (unsigned)TOPK) { seg = t; before = cum; break; }
            cum += segsum[t];
        }
        unsigned c2 = before; unsigned th = 0;
        for (int b = 63; b >= 0; b--) {
            c2 += g_hist[lv][seg * 64 + b];
            if (c2 >= (unsigned)TOPK) { th = ((unsigned)(seg * 64 + b)) << 16; break; }
        }
        g_thresh[lv] = th;
    }
}

__global__ void compact_all_kernel() {
    int lv = blockIdx.y;
    int HW = c_HW[lv];
    int i = blockIdx.x * blockDim.x + threadIdx.x;
    if (i >= HW) return;
    if (g_bits[lv][i] >= g_thresh[lv]) {
        int p = atomicAdd(&g_ncand[lv], 1);
        g_cand[lv][p] = i;
    }
}

// rank candidates (exact lax.top_k semantics: value desc, index asc), emit topk rows
__global__ void rank_level_all_kernel(const float* __restrict__ reg0,
                                      const float* __restrict__ reg1,
                                      const float* __restrict__ reg2,
                                      const float* __restrict__ scales) {
    int lv = blockIdx.y;
    const float* reg = (lv == 0) ? reg0 : (lv == 1) ? reg1 : reg2;
    int HW = c_HW[lv], W = c_W[lv];
    float stride = c_strd[lv];
    int ncand = g_ncand[lv];
    if ((int)(blockIdx.x * blockDim.x) >= ncand) return;   // whole-block uniform
    int c = blockIdx.x * blockDim.x + threadIdx.x;
    __shared__ unsigned long long skey[256];
    bool active = (c < ncand);
    unsigned mybits = 0; int myidx = 0;
    unsigned long long mykey = 0;
    if (active) {
        myidx = g_cand[lv][c];
        mybits = g_bits[lv][myidx];
        mykey = ((unsigned long long)mybits << 32) | (unsigned)(~(unsigned)myidx);
    }
    int rank = 0;
    for (int base = 0; base < ncand; base += 256) {
        int j = base + (int)threadIdx.x;
        unsigned long long k = 0;
        if (j < ncand) {
            int ji = g_cand[lv][j];
            k = ((unsigned long long)g_bits[lv][ji] << 32) | (unsigned)(~(unsigned)ji);
        }
        __syncthreads();
        skey[threadIdx.x] = k;
        __syncthreads();
        int lim = min(256, ncand - base);
        if (active)
            for (int t = 0; t < lim; t++) rank += (skey[t] > mykey) ? 1 : 0;
    }
    if (active && rank < TOPK) {
        int o = lv * TOPK + rank;
        t_bits[o]  = mybits;
        t_label[o] = g_label[lv][myidx];
        float sc = scales[lv];
        int x = myidx % W, y = myidx / W;
        float ax = ((float)x + 0.5f) * stride;
        float ay = ((float)y + 0.5f) * stride;
        float r0 = fmaxf(reg[0 * HW + myidx] * sc, 0.0f) * stride;
        float r1 = fmaxf(reg[1 * HW + myidx] * sc, 0.0f) * stride;
        float r2 = fmaxf(reg[2 * HW + myidx] * sc, 0.0f) * stride;
        float r3 = fmaxf(reg[3 * HW + myidx] * sc, 0.0f) * stride;
        t_box[o][0] = ax - r0; t_box[o][1] = ay - r1;
        t_box[o][2] = ax + r2; t_box[o][3] = ay + r3;
    }
}

// stable argsort(-scores) over the 3000 concatenated entries via rank counting
__global__ void rank_global_kernel() {
    int g = blockIdx.x * blockDim.x + threadIdx.x;
    __shared__ unsigned long long skey[256];
    bool active = (g < NTOT);
    unsigned long long mykey = 0;
    if (active) mykey = ((unsigned long long)t_bits[g] << 32) | (unsigned)(~(unsigned)g);
    int rank = 0;
    for (int base = 0; base < NTOT; base += 256) {
        int j = base + (int)threadIdx.x;
        unsigned long long k = 0;
        if (j < NTOT) k = ((unsigned long long)t_bits[j] << 32) | (unsigned)(~(unsigned)j);
        __syncthreads();
        skey[threadIdx.x] = k;
        __syncthreads();
        int lim = min(256, NTOT - base);
        if (active)
            for (int t = 0; t < lim; t++) rank += (skey[t] > mykey) ? 1 : 0;
    }
    if (active) {
        s_score[rank] = __uint_as_float(t_bits[g]);
        s_label[rank] = t_label[g];
        s_box[rank][0] = t_box[g][0];
        s_box[rank][1] = t_box[g][1];
        s_box[rank][2] = t_box[g][2];
        s_box[rank][3] = t_box[g][3];
    }
}

// suppression bitmask: bit j (j>i) set iff IoU(i,j) > 0.6
// triangle-pruned (skipped blocks are provably never read); exact IoU math
__global__ void mask_kernel() {
    int w  = blockIdx.x;                 // word 0..46  (j in [64w, 64w+64))
    int by = blockIdx.y;                 // i-block     (i in [256by, 256by+256))
    if (w < 4 * by) return;              // all j < all i in this block: never read
    __shared__ float jb[64][4];
    __shared__ float ja[64];
    int jlim = min(64, NTOT - w * 64);
    if ((int)threadIdx.x < jlim) {
        int j = w * 64 + threadIdx.x;
        float x1 = s_box[j][0], y1 = s_box[j][1], x2 = s_box[j][2], y2 = s_box[j][3];
        jb[threadIdx.x][0] = x1; jb[threadIdx.x][1] = y1;
        jb[threadIdx.x][2] = x2; jb[threadIdx.x][3] = y2;
        ja[threadIdx.x] = (x2 - x1) * (y2 - y1);
    }
    __syncthreads();
    int i = by * 256 + threadIdx.x;
    if (i >= NTOT) return;
    float ix1 = s_box[i][0], iy1 = s_box[i][1], ix2 = s_box[i][2], iy2 = s_box[i][3];
    float ia = (ix2 - ix1) * (iy2 - iy1);
    unsigned long long bits = 0;
    for (int b = 0; b < jlim; b++) {
        int j = w * 64 + b;
        if (j > i) {
            float xx1 = fmaxf(ix1, jb[b][0]);
            float yy1 = fmaxf(iy1, jb[b][1]);
            float xx2 = fminf(ix2, jb[b][2]);
            float yy2 = fminf(iy2, jb[b][3]);
            float ww = fmaxf(1e-10f, xx2 - xx1);
            float hh = fmaxf(1e-10f, yy2 - yy1);
            float inter = ww * hh;
            float iou = inter / (ia + ja[b] - inter + 1e-14f);
            if (iou > NMS_TH) bits |= (1ull << b);
        }
    }
    g_mask[i][w] = bits;
}

// greedy NMS scan — proven structure (single staged column, 3 syncs/iter)
__global__ void nms_kernel() {
    __shared__ unsigned long long remv[NW];
    __shared__ unsigned long long col[64];
    __shared__ unsigned long long sh_kept;
    int tid = threadIdx.x;   // 256
    if (tid < NW) remv[tid] = 0ull;
    __syncthreads();
    for (int c = 0; c < NW; c++) {
        int base = c * 64;
        int lim = min(64, NTOT - base);
        // stage mask column c for rows [base, base+64) into smem (parallel loads)
        if (tid < 64) col[tid] = (tid < lim) ? g_mask[base + tid][c] : 0ull;
        __syncthreads();
        if (tid == 0) {
            unsigned long long r = remv[c], kept = 0;
            #pragma unroll
            for (int b = 0; b < 64; b++) {
                unsigned long long v = col[b];           // address indep of r -> pipelined
                if (!((r >> b) & 1ull)) { kept |= (1ull << b); r |= v; }
            }
            if (lim < 64) kept &= (1ull << lim) - 1ull;
            remv[c] = r;
            sh_kept = kept;
        }
        __syncthreads();
        unsigned long long kept = sh_kept;
        int nw_rem = NW - c - 1;
        // 4 threads per remaining word, each handles a 16-bit slice of kept
        for (int t = tid; t < nw_rem * 4; t += (int)blockDim.x) {
            int w = c + 1 + (t >> 2);
            int q = t & 3;
            unsigned long long k = kept & (0xFFFFull << (q * 16));
            unsigned long long acc = 0;
            while (k) {
                int b = __ffsll((long long)k) - 1;
                acc |= g_mask[base + b][w];
                k &= k - 1;
            }
            if (acc) atomicOr(&remv[w], acc);
        }
        __syncthreads();
    }
    if (tid < NW) g_keep[tid] = remv[tid];
}

// final output write: [boxes 12000][scores 3000][labels 3000][keep 3000] all f32
__global__ void finalize_kernel(float* __restrict__ out) {
    int i = blockIdx.x * blockDim.x + threadIdx.x;
    if (i >= NTOT) return;
    out[i * 4 + 0] = s_box[i][0];
    out[i * 4 + 1] = s_box[i][1];
    out[i * 4 + 2] = s_box[i][2];
    out[i * 4 + 3] = s_box[i][3];
    float sc = s_score[i];
    out[12000 + i] = sc;
    out[15000 + i] = (float)s_label[i];
    bool kp = !((g_keep[i >> 6] >> (i & 63)) & 1ull) && (sc > CONF_TH);
    out[18000 + i] = kp ? 1.0f : 0.0f;
}

// ---------------- launch ----------------
extern "C" void kernel_launch(void* const* d_in, const int* in_sizes, int n_in,
                              void* d_out, int out_size) {
    const float *cls[3], *reg[3], *ctn[3], *scales;
    if (in_sizes[1] == 262144) {
        cls[0] = (const float*)d_in[0]; reg[0] = (const float*)d_in[1]; ctn[0] = (const float*)d_in[2];
        cls[1] = (const float*)d_in[3]; reg[1] = (const float*)d_in[4]; ctn[1] = (const float*)d_in[5];
        cls[2] = (const float*)d_in[6]; reg[2] = (const float*)d_in[7]; ctn[2] = (const float*)d_in[8];
        scales = (const float*)d_in[9];
    } else if (in_sizes[3] == 262144) {
        cls[0] = (const float*)d_in[0]; cls[1] = (const float*)d_in[1]; cls[2] = (const float*)d_in[2];
        reg[0] = (const float*)d_in[3]; reg[1] = (const float*)d_in[4]; reg[2] = (const float*)d_in[5];
        ctn[0] = (const float*)d_in[6]; ctn[1] = (const float*)d_in[7]; ctn[2] = (const float*)d_in[8];
        scales = (const float*)d_in[9];
    } else {
        cls[0] = (const float*)d_in[0]; cls[1] = (const float*)d_in[1]; cls[2] = (const float*)d_in[2];
        ctn[0] = (const float*)d_in[3]; ctn[1] = (const float*)d_in[4]; ctn[2] = (const float*)d_in[5];
        reg[0] = (const float*)d_in[6]; reg[1] = (const float*)d_in[7]; reg[2] = (const float*)d_in[8];
        scales = (const float*)d_in[9];
    }

    zero_kernel<<<(NLEV * 65536 + 255) / 256, 256>>>();
    decode_all_kernel<<<256 + 64 + 16, 256>>>(cls[0], cls[1], cls[2],
                                              ctn[0], ctn[1], ctn[2]);
    thresh_kernel<<<3, 1024>>>();
    {
        dim3 g(256, 3);
        compact_all_kernel<<<g, 256>>>();
        rank_level_all_kernel<<<g, 256>>>(reg[0], reg[1], reg[2], scales);
    }
    rank_global_kernel<<<(NTOT + 255) / 256, 256>>>();
    {
        dim3 grid(NW, (NTOT + 255) / 256);
        mask_kernel<<<grid, 256>>>();
    }
    nms_kernel<<<1, 256>>>();
    finalize_kernel<<<(NTOT + 255) / 256, 256>>>((float*)d_out);
}